// round 1
// baseline (speedup 1.0000x reference)
#include <cuda_runtime.h>
#include <math.h>

// Problem constants
#define BATCH 2
#define SEQ   2048
#define EMB   2048
#define NHEAD 16
#define DHEAD 128
#define NEXP_ 64
#define RLORA 32
#define ROWS  4096          // BATCH*SEQ
#define KAUG  2144          // EMB + RLORA + NEXP_

// ---------------- scratch (static device globals; no allocations) ----------
__device__ float g_q[(size_t)ROWS * EMB];
__device__ float g_k[(size_t)ROWS * EMB];
__device__ float g_v[(size_t)ROWS * EMB];
__device__ float g_att[(size_t)ROWS * EMB];
__device__ float g_haux[4][(size_t)ROWS * 96];   // per-proj [silu(xA^T)|silu(xC^T)*mask]

// ---------------------------------------------------------------------------
// Aux kernel: for up to 3 projections, compute haux[row, 0:32]  = silu(x@A^T)
//                                        haux[row, 32:96] = silu(x@C^T)*mask
// one block per row; 288 threads = 3 proj * 96 outputs
// ---------------------------------------------------------------------------
__global__ void haux_kernel(const float* __restrict__ x,
                            const float* __restrict__ mask,
                            const float* __restrict__ A0, const float* __restrict__ C0,
                            const float* __restrict__ A1, const float* __restrict__ C1,
                            const float* __restrict__ A2, const float* __restrict__ C2,
                            float* __restrict__ h0, float* __restrict__ h1,
                            float* __restrict__ h2, int nproj)
{
    __shared__ float xs[EMB];
    const int row = blockIdx.x;
    const float* xr = x + (size_t)row * EMB;
    for (int i = threadIdx.x; i < EMB / 4; i += blockDim.x) {
        float4 v = *(const float4*)(xr + i * 4);
        *(float4*)&xs[i * 4] = v;
    }
    __syncthreads();

    int t = threadIdx.x;
    int proj = t / 96, u = t % 96;
    if (proj >= nproj) return;

    const float* A = (proj == 0) ? A0 : ((proj == 1) ? A1 : A2);
    const float* C = (proj == 0) ? C0 : ((proj == 1) ? C1 : C2);
    float* hout    = (proj == 0) ? h0 : ((proj == 1) ? h1 : h2);

    const float* wrow = (u < 32) ? (A + (size_t)u * EMB)
                                 : (C + (size_t)(u - 32) * EMB);
    float acc = 0.f;
    #pragma unroll 4
    for (int k = 0; k < EMB; k += 4) {
        float4 w = *(const float4*)&wrow[k];
        acc += xs[k] * w.x + xs[k + 1] * w.y + xs[k + 2] * w.z + xs[k + 3] * w.w;
    }
    float s = acc / (1.f + expf(-acc));   // silu
    if (u >= 32) s *= mask[(size_t)row * NEXP_ + (u - 32)];
    hout[(size_t)row * 96 + u] = s;
}

// ---------------------------------------------------------------------------
// K-augmented GEMM:  out[M=4096, N=2048] = sum_k a(m,k) * w(n,k) (+ bias[n])
//   k in [0,2048)      : a = act,  w = W
//   k in [2048,2080)   : a = haux, w = Bl (LoRA up),   * SCALE (=1.0)
//   k in [2080,2144)   : a = haux, w = Rr (expert rows)
// 128x128x16 tile, 256 threads, 8x8 microtile
// ---------------------------------------------------------------------------
#define BM 128
#define BN 128
#define BKg 16

__global__ __launch_bounds__(256) void gemm_aug(
    const float* __restrict__ act, const float* __restrict__ haux,
    const float* __restrict__ Wd,  const float* __restrict__ Bl,
    const float* __restrict__ Rr,  const float* __restrict__ bias,
    float* __restrict__ out)
{
    __shared__ float As[BKg][BM + 4];
    __shared__ float Bs[BKg][BN + 4];
    const int tid = threadIdx.x;
    const int ty = tid >> 4, tx = tid & 15;
    const int m0 = blockIdx.y * BM, n0 = blockIdx.x * BN;

    float c[8][8];
    #pragma unroll
    for (int i = 0; i < 8; i++)
        #pragma unroll
        for (int j = 0; j < 8; j++) c[i][j] = 0.f;

    for (int k0 = 0; k0 < KAUG; k0 += BKg) {
        const float* asrc; int lda, kof;
        if (k0 < EMB) { asrc = act;  lda = EMB; kof = k0; }
        else          { asrc = haux; lda = 96;  kof = k0 - EMB; }

        const float* wsrc; int ldw, kofw;
        if (k0 < EMB)             { wsrc = Wd; ldw = EMB;   kofw = k0; }
        else if (k0 < EMB + RLORA){ wsrc = Bl; ldw = RLORA; kofw = k0 - EMB; }
        else                      { wsrc = Rr; ldw = NEXP_; kofw = k0 - EMB - RLORA; }

        #pragma unroll
        for (int i = 0; i < 2; i++) {
            int lin = tid + 256 * i;            // 0..511 float4 slots
            int r = lin >> 2, c4 = (lin & 3) << 2;
            float4 va = *(const float4*)(asrc + (size_t)(m0 + r) * lda + kof + c4);
            As[c4 + 0][r] = va.x; As[c4 + 1][r] = va.y;
            As[c4 + 2][r] = va.z; As[c4 + 3][r] = va.w;
            float4 vb = *(const float4*)(wsrc + (size_t)(n0 + r) * ldw + kofw + c4);
            Bs[c4 + 0][r] = vb.x; Bs[c4 + 1][r] = vb.y;
            Bs[c4 + 2][r] = vb.z; Bs[c4 + 3][r] = vb.w;
        }
        __syncthreads();

        #pragma unroll
        for (int kk = 0; kk < BKg; kk++) {
            float a[8], b[8];
            *(float4*)&a[0] = *(const float4*)&As[kk][ty * 8];
            *(float4*)&a[4] = *(const float4*)&As[kk][ty * 8 + 4];
            *(float4*)&b[0] = *(const float4*)&Bs[kk][tx * 8];
            *(float4*)&b[4] = *(const float4*)&Bs[kk][tx * 8 + 4];
            #pragma unroll
            for (int i = 0; i < 8; i++)
                #pragma unroll
                for (int j = 0; j < 8; j++)
                    c[i][j] += a[i] * b[j];
        }
        __syncthreads();
    }

    #pragma unroll
    for (int i = 0; i < 8; i++) {
        size_t row = (size_t)(m0 + ty * 8 + i);
        #pragma unroll
        for (int j = 0; j < 8; j++) {
            int col = n0 + tx * 8 + j;
            float val = c[i][j];
            if (bias) val += bias[col];
            out[row * EMB + col] = val;
        }
    }
}

// ---------------------------------------------------------------------------
// RoPE (in-place on q and k): llama rotate_half form
// ---------------------------------------------------------------------------
__global__ void rope_kernel(float* __restrict__ q, float* __restrict__ k)
{
    int idx = blockIdx.x * blockDim.x + threadIdx.x;   // ROWS*NHEAD*64
    if (idx >= ROWS * NHEAD * 64) return;
    int j   = idx & 63;
    int h   = (idx >> 6) & 15;
    int row = idx >> 10;
    int s   = row & (SEQ - 1);

    float e   = (float)(2 * j) * (1.0f / 128.0f);
    float inv = powf(10000.0f, -e);
    float ang = (float)s * inv;
    float sn, cs;
    sincosf(ang, &sn, &cs);

    size_t base = (size_t)row * EMB + h * DHEAD + j;
    float x1 = q[base], x2 = q[base + 64];
    q[base]      = x1 * cs - x2 * sn;
    q[base + 64] = x2 * cs + x1 * sn;
    x1 = k[base]; x2 = k[base + 64];
    k[base]      = x1 * cs - x2 * sn;
    k[base + 64] = x2 * cs + x1 * sn;
}

// ---------------------------------------------------------------------------
// Causal flash attention, fp32. 64x64 tiles, D=128, 256 threads.
// smem: Qs[64][132] + KVs[64][132] (K then V reuse) + Ps[64][68]
// ---------------------------------------------------------------------------
#define FDP 132
#define FNP 68
#define FA_SMEM ((64 * FDP * 2 + 64 * FNP) * 4)

__global__ __launch_bounds__(256) void flash_kernel(
    const float* __restrict__ q, const float* __restrict__ k,
    const float* __restrict__ v, float* __restrict__ o)
{
    extern __shared__ float sm[];
    float* Qs  = sm;
    float* KVs = sm + 64 * FDP;
    float* Ps  = KVs + 64 * FDP;

    const int tid = threadIdx.x;
    const int ty = tid >> 4, tx = tid & 15;
    const int iblk = blockIdx.x;                 // query tile
    const int bh = blockIdx.y;
    const int b = bh >> 4, h = bh & 15;
    const size_t rowbase = (size_t)b * SEQ;
    const int m0 = iblk * 64;
    const float scale = 0.08838834764831845f;    // 1/sqrt(128)

    // load Q tile (pre-scaled)
    #pragma unroll
    for (int i = 0; i < 8; i++) {
        int lin = tid + 256 * i;                 // 2048 float4
        int r = lin >> 5, c4 = (lin & 31) << 2;
        float4 vq = *(const float4*)(q + ((rowbase + m0 + r) * EMB + h * DHEAD + c4));
        vq.x *= scale; vq.y *= scale; vq.z *= scale; vq.w *= scale;
        *(float4*)&Qs[r * FDP + c4] = vq;
    }

    float m_i[4], l_i[4], acc[4][8];
    #pragma unroll
    for (int i = 0; i < 4; i++) {
        m_i[i] = -1e30f; l_i[i] = 0.f;
        #pragma unroll
        for (int d = 0; d < 8; d++) acc[i][d] = 0.f;
    }
    __syncthreads();

    for (int j = 0; j <= iblk; j++) {
        // load K tile
        #pragma unroll
        for (int i = 0; i < 8; i++) {
            int lin = tid + 256 * i;
            int r = lin >> 5, c4 = (lin & 31) << 2;
            *(float4*)&KVs[r * FDP + c4] =
                *(const float4*)(k + ((rowbase + j * 64 + r) * EMB + h * DHEAD + c4));
        }
        __syncthreads();

        // S = Q K^T
        float s[4][4];
        #pragma unroll
        for (int i = 0; i < 4; i++)
            #pragma unroll
            for (int jj = 0; jj < 4; jj++) s[i][jj] = 0.f;

        for (int d = 0; d < DHEAD; d += 4) {
            float4 qa[4], kb[4];
            #pragma unroll
            for (int i = 0; i < 4; i++) qa[i] = *(const float4*)&Qs[(ty * 4 + i) * FDP + d];
            #pragma unroll
            for (int i = 0; i < 4; i++) kb[i] = *(const float4*)&KVs[(tx * 4 + i) * FDP + d];
            #pragma unroll
            for (int i = 0; i < 4; i++)
                #pragma unroll
                for (int jj = 0; jj < 4; jj++)
                    s[i][jj] += qa[i].x * kb[jj].x + qa[i].y * kb[jj].y +
                                qa[i].z * kb[jj].z + qa[i].w * kb[jj].w;
        }

        if (j == iblk) {   // causal mask, diagonal tile
            #pragma unroll
            for (int i = 0; i < 4; i++)
                #pragma unroll
                for (int jj = 0; jj < 4; jj++)
                    if (j * 64 + tx * 4 + jj > m0 + ty * 4 + i) s[i][jj] = -1e30f;
        }

        // online softmax
        float alpha[4];
        #pragma unroll
        for (int i = 0; i < 4; i++) {
            float rm = fmaxf(fmaxf(s[i][0], s[i][1]), fmaxf(s[i][2], s[i][3]));
            #pragma unroll
            for (int off = 1; off < 16; off <<= 1)
                rm = fmaxf(rm, __shfl_xor_sync(0xffffffffu, rm, off));
            float mnew = fmaxf(m_i[i], rm);
            alpha[i] = __expf(m_i[i] - mnew);
            m_i[i] = mnew;
            float rs = 0.f;
            #pragma unroll
            for (int jj = 0; jj < 4; jj++) {
                float p = __expf(s[i][jj] - mnew);
                s[i][jj] = p;
                rs += p;
            }
            #pragma unroll
            for (int off = 1; off < 16; off <<= 1)
                rs += __shfl_xor_sync(0xffffffffu, rs, off);
            l_i[i] = l_i[i] * alpha[i] + rs;
            #pragma unroll
            for (int jj = 0; jj < 4; jj++)
                Ps[(ty * 4 + i) * FNP + tx * 4 + jj] = s[i][jj];
            #pragma unroll
            for (int d = 0; d < 8; d++) acc[i][d] *= alpha[i];
        }
        __syncthreads();   // all K reads & P writes done

        // load V tile into the same buffer
        #pragma unroll
        for (int i = 0; i < 8; i++) {
            int lin = tid + 256 * i;
            int r = lin >> 5, c4 = (lin & 31) << 2;
            *(float4*)&KVs[r * FDP + c4] =
                *(const float4*)(v + ((rowbase + j * 64 + r) * EMB + h * DHEAD + c4));
        }
        __syncthreads();

        // O += P V
        for (int n = 0; n < 64; n++) {
            float p[4];
            #pragma unroll
            for (int i = 0; i < 4; i++) p[i] = Ps[(ty * 4 + i) * FNP + n];
            float4 va = *(const float4*)&KVs[n * FDP + tx * 8];
            float4 vb = *(const float4*)&KVs[n * FDP + tx * 8 + 4];
            #pragma unroll
            for (int i = 0; i < 4; i++) {
                acc[i][0] += p[i] * va.x; acc[i][1] += p[i] * va.y;
                acc[i][2] += p[i] * va.z; acc[i][3] += p[i] * va.w;
                acc[i][4] += p[i] * vb.x; acc[i][5] += p[i] * vb.y;
                acc[i][6] += p[i] * vb.z; acc[i][7] += p[i] * vb.w;
            }
        }
        __syncthreads();   // before next K load / P overwrite
    }

    #pragma unroll
    for (int i = 0; i < 4; i++) {
        float invl = 1.f / l_i[i];
        size_t base = (rowbase + m0 + ty * 4 + i) * EMB + h * DHEAD + tx * 8;
        #pragma unroll
        for (int d = 0; d < 8; d++)
            o[base + d] = acc[i][d] * invl;
    }
}

// ---------------------------------------------------------------------------
extern "C" void kernel_launch(void* const* d_in, const int* in_sizes, int n_in,
                              void* d_out, int out_size)
{
    const float* x    = (const float*)d_in[0];
    const float* mask = (const float*)d_in[1];
    const float* Wq = (const float*)d_in[2];  const float* bq = (const float*)d_in[3];
    const float* Aq = (const float*)d_in[4];  const float* Bq = (const float*)d_in[5];
    const float* Cq = (const float*)d_in[6];  const float* Rq = (const float*)d_in[7];
    const float* Wk = (const float*)d_in[8];  const float* bk = (const float*)d_in[9];
    const float* Ak = (const float*)d_in[10]; const float* Bk = (const float*)d_in[11];
    const float* Ck = (const float*)d_in[12]; const float* Rk = (const float*)d_in[13];
    const float* Wv = (const float*)d_in[14]; const float* bv = (const float*)d_in[15];
    const float* Av = (const float*)d_in[16]; const float* Bv = (const float*)d_in[17];
    const float* Cv = (const float*)d_in[18]; const float* Rv = (const float*)d_in[19];
    const float* Wo = (const float*)d_in[20]; const float* Ao = (const float*)d_in[21];
    const float* Bo = (const float*)d_in[22]; const float* Co = (const float*)d_in[23];
    const float* Ro = (const float*)d_in[24];

    float *q, *k, *v, *att, *hx;
    cudaGetSymbolAddress((void**)&q,   g_q);
    cudaGetSymbolAddress((void**)&k,   g_k);
    cudaGetSymbolAddress((void**)&v,   g_v);
    cudaGetSymbolAddress((void**)&att, g_att);
    cudaGetSymbolAddress((void**)&hx,  g_haux);
    float* hq = hx;
    float* hk = hx + (size_t)ROWS * 96;
    float* hv = hx + (size_t)ROWS * 96 * 2;
    float* ho = hx + (size_t)ROWS * 96 * 3;

    cudaFuncSetAttribute(flash_kernel,
                         cudaFuncAttributeMaxDynamicSharedMemorySize, FA_SMEM);

    dim3 ggrid(EMB / BN, ROWS / BM);   // (16, 32)

    // aux terms for q/k/v
    haux_kernel<<<ROWS, 288>>>(x, mask, Aq, Cq, Ak, Ck, Av, Cv, hq, hk, hv, 3);
    // projections (K-augmented GEMMs)
    gemm_aug<<<ggrid, 256>>>(x, hq, Wq, Bq, Rq, bq, q);
    gemm_aug<<<ggrid, 256>>>(x, hk, Wk, Bk, Rk, bk, k);
    gemm_aug<<<ggrid, 256>>>(x, hv, Wv, Bv, Rv, bv, v);
    // rope on q,k
    rope_kernel<<<(ROWS * NHEAD * 64 + 255) / 256, 256>>>(q, k);
    // causal flash attention
    flash_kernel<<<dim3(SEQ / 64, BATCH * NHEAD), 256, FA_SMEM>>>(q, k, v, att);
    // output projection (no bias)
    haux_kernel<<<ROWS, 288>>>(att, mask, Ao, Co, Ao, Co, Ao, Co, ho, ho, ho, 1);
    gemm_aug<<<ggrid, 256>>>(att, ho, Wo, Bo, Ro, nullptr, (float*)d_out);
}

// round 2
// speedup vs baseline: 1.4109x; 1.4109x over previous
#include <cuda_runtime.h>
#include <math.h>

// Problem constants
#define BATCH 2
#define SEQ   2048
#define EMB   2048
#define NHEAD 16
#define DHEAD 128
#define NEXP_ 64
#define RLORA 32
#define ROWS  4096          // BATCH*SEQ
#define KAUG  2144          // EMB + RLORA + NEXP_

// ---------------- scratch (static device globals; no allocations) ----------
__device__ float g_q[(size_t)ROWS * EMB];
__device__ float g_k[(size_t)ROWS * EMB];
__device__ float g_v[(size_t)ROWS * EMB];
__device__ float g_att[(size_t)ROWS * EMB];
__device__ float g_haux[4][(size_t)ROWS * 96];   // per-proj [silu(xA^T)|silu(xC^T)*mask]

// ---------------------------------------------------------------------------
// aux GEMM: h[row, 0:32]  = silu(x@A^T)
//           h[row, 32:96] = silu(x@C^T)*mask
// Tiled GEMM 128x96x16, 256 threads, 8x6 microtile. blockIdx.x selects proj.
// ---------------------------------------------------------------------------
__global__ __launch_bounds__(256) void aux_gemm(
    const float* __restrict__ act, const float* __restrict__ mask,
    const float* __restrict__ A0, const float* __restrict__ C0,
    const float* __restrict__ A1, const float* __restrict__ C1,
    const float* __restrict__ A2, const float* __restrict__ C2,
    float* __restrict__ h0, float* __restrict__ h1, float* __restrict__ h2)
{
    __shared__ float As[16][132];
    __shared__ float Bs[16][100];

    const int proj = blockIdx.x;
    const int m0 = blockIdx.y * 128;
    const float* A = (proj == 0) ? A0 : ((proj == 1) ? A1 : A2);
    const float* C = (proj == 0) ? C0 : ((proj == 1) ? C1 : C2);
    float* hout    = (proj == 0) ? h0 : ((proj == 1) ? h1 : h2);

    const int tid = threadIdx.x;
    const int ty = tid >> 4, tx = tid & 15;

    float acc[8][6];
    #pragma unroll
    for (int i = 0; i < 8; i++)
        #pragma unroll
        for (int j = 0; j < 6; j++) acc[i][j] = 0.f;

    for (int k0 = 0; k0 < EMB; k0 += 16) {
        // As: 128 rows x 16 k = 512 float4 slots
        #pragma unroll
        for (int i = 0; i < 2; i++) {
            int lin = tid + 256 * i;
            int r = lin >> 2, c4 = (lin & 3) << 2;
            float4 va = *(const float4*)(act + (size_t)(m0 + r) * EMB + k0 + c4);
            As[c4 + 0][r] = va.x; As[c4 + 1][r] = va.y;
            As[c4 + 2][r] = va.z; As[c4 + 3][r] = va.w;
        }
        // Bs: 96 rows x 16 k = 384 float4 slots
        #pragma unroll
        for (int i = 0; i < 2; i++) {
            int lin = tid + 256 * i;
            if (lin < 384) {
                int r = lin >> 2, c4 = (lin & 3) << 2;
                const float* src = (r < 32) ? (A + (size_t)r * EMB)
                                            : (C + (size_t)(r - 32) * EMB);
                float4 vb = *(const float4*)(src + k0 + c4);
                Bs[c4 + 0][r] = vb.x; Bs[c4 + 1][r] = vb.y;
                Bs[c4 + 2][r] = vb.z; Bs[c4 + 3][r] = vb.w;
            }
        }
        __syncthreads();

        #pragma unroll
        for (int kk = 0; kk < 16; kk++) {
            float a[8], b[6];
            *(float4*)&a[0] = *(const float4*)&As[kk][ty * 8];
            *(float4*)&a[4] = *(const float4*)&As[kk][ty * 8 + 4];
            #pragma unroll
            for (int j = 0; j < 6; j++) b[j] = Bs[kk][tx * 6 + j];
            #pragma unroll
            for (int i = 0; i < 8; i++)
                #pragma unroll
                for (int j = 0; j < 6; j++)
                    acc[i][j] += a[i] * b[j];
        }
        __syncthreads();
    }

    #pragma unroll
    for (int i = 0; i < 8; i++) {
        int row = m0 + ty * 8 + i;
        #pragma unroll
        for (int j = 0; j < 6; j++) {
            int u = tx * 6 + j;
            float v = acc[i][j];
            float s = v / (1.f + expf(-v));            // silu
            if (u >= 32) s *= mask[(size_t)row * NEXP_ + (u - 32)];
            hout[(size_t)row * 96 + u] = s;
        }
    }
}

// ---------------------------------------------------------------------------
// K-augmented GEMM:  out[M=4096, N=2048] = sum_k a(m,k) * w(n,k) (+ bias[n])
//   k in [0,2048)      : a = act,  w = W
//   k in [2048,2080)   : a = haux, w = Bl (LoRA up)
//   k in [2080,2144)   : a = haux, w = Rr (expert rows)
// 128x256x16 tile, 256 threads, 8x16 microtile with interleaved b columns.
// ---------------------------------------------------------------------------
#define BM 128
#define BN 256
#define BKg 16

__global__ __launch_bounds__(256) void gemm_aug(
    const float* __restrict__ act, const float* __restrict__ haux,
    const float* __restrict__ Wd,  const float* __restrict__ Bl,
    const float* __restrict__ Rr,  const float* __restrict__ bias,
    float* __restrict__ out)
{
    __shared__ float As[BKg][BM + 4];
    __shared__ float Bs[BKg][BN + 4];
    const int tid = threadIdx.x;
    const int ty = tid >> 4, tx = tid & 15;
    const int m0 = blockIdx.y * BM, n0 = blockIdx.x * BN;

    float c[8][16];
    #pragma unroll
    for (int i = 0; i < 8; i++)
        #pragma unroll
        for (int j = 0; j < 16; j++) c[i][j] = 0.f;

    for (int k0 = 0; k0 < KAUG; k0 += BKg) {
        const float* asrc; int lda, kof;
        if (k0 < EMB) { asrc = act;  lda = EMB; kof = k0; }
        else          { asrc = haux; lda = 96;  kof = k0 - EMB; }

        const float* wsrc; int ldw, kofw;
        if (k0 < EMB)             { wsrc = Wd; ldw = EMB;   kofw = k0; }
        else if (k0 < EMB + RLORA){ wsrc = Bl; ldw = RLORA; kofw = k0 - EMB; }
        else                      { wsrc = Rr; ldw = NEXP_; kofw = k0 - EMB - RLORA; }

        // As: 128 rows x 16 = 512 float4 slots
        #pragma unroll
        for (int i = 0; i < 2; i++) {
            int lin = tid + 256 * i;
            int r = lin >> 2, c4 = (lin & 3) << 2;
            float4 va = *(const float4*)(asrc + (size_t)(m0 + r) * lda + kof + c4);
            As[c4 + 0][r] = va.x; As[c4 + 1][r] = va.y;
            As[c4 + 2][r] = va.z; As[c4 + 3][r] = va.w;
        }
        // Bs: 256 rows x 16 = 1024 float4 slots
        #pragma unroll
        for (int i = 0; i < 4; i++) {
            int lin = tid + 256 * i;
            int r = lin >> 2, c4 = (lin & 3) << 2;
            float4 vb = *(const float4*)(wsrc + (size_t)(n0 + r) * ldw + kofw + c4);
            Bs[c4 + 0][r] = vb.x; Bs[c4 + 1][r] = vb.y;
            Bs[c4 + 2][r] = vb.z; Bs[c4 + 3][r] = vb.w;
        }
        __syncthreads();

        #pragma unroll
        for (int kk = 0; kk < BKg; kk++) {
            float a[8];
            float4 b[4];
            *(float4*)&a[0] = *(const float4*)&As[kk][ty * 8];
            *(float4*)&a[4] = *(const float4*)&As[kk][ty * 8 + 4];
            #pragma unroll
            for (int cb = 0; cb < 4; cb++)
                b[cb] = *(const float4*)&Bs[kk][cb * 64 + tx * 4];
            #pragma unroll
            for (int i = 0; i < 8; i++) {
                #pragma unroll
                for (int cb = 0; cb < 4; cb++) {
                    c[i][cb * 4 + 0] += a[i] * b[cb].x;
                    c[i][cb * 4 + 1] += a[i] * b[cb].y;
                    c[i][cb * 4 + 2] += a[i] * b[cb].z;
                    c[i][cb * 4 + 3] += a[i] * b[cb].w;
                }
            }
        }
        __syncthreads();
    }

    // bias fragments (column-dependent only)
    float4 bv[4];
    #pragma unroll
    for (int cb = 0; cb < 4; cb++) {
        if (bias) bv[cb] = *(const float4*)(bias + n0 + cb * 64 + tx * 4);
        else      bv[cb] = make_float4(0.f, 0.f, 0.f, 0.f);
    }

    #pragma unroll
    for (int i = 0; i < 8; i++) {
        size_t row = (size_t)(m0 + ty * 8 + i);
        #pragma unroll
        for (int cb = 0; cb < 4; cb++) {
            int col = n0 + cb * 64 + tx * 4;
            float4 o;
            o.x = c[i][cb * 4 + 0] + bv[cb].x;
            o.y = c[i][cb * 4 + 1] + bv[cb].y;
            o.z = c[i][cb * 4 + 2] + bv[cb].z;
            o.w = c[i][cb * 4 + 3] + bv[cb].w;
            *(float4*)(out + row * EMB + col) = o;
        }
    }
}

// ---------------------------------------------------------------------------
// RoPE (in-place on q and k): llama rotate_half form
// ---------------------------------------------------------------------------
__global__ void rope_kernel(float* __restrict__ q, float* __restrict__ k)
{
    int idx = blockIdx.x * blockDim.x + threadIdx.x;   // ROWS*NHEAD*64
    if (idx >= ROWS * NHEAD * 64) return;
    int j   = idx & 63;
    int h   = (idx >> 6) & 15;
    int row = idx >> 10;
    int s   = row & (SEQ - 1);

    float e   = (float)(2 * j) * (1.0f / 128.0f);
    float inv = powf(10000.0f, -e);
    float ang = (float)s * inv;
    float sn, cs;
    sincosf(ang, &sn, &cs);

    size_t base = (size_t)row * EMB + h * DHEAD + j;
    float x1 = q[base], x2 = q[base + 64];
    q[base]      = x1 * cs - x2 * sn;
    q[base + 64] = x2 * cs + x1 * sn;
    x1 = k[base]; x2 = k[base + 64];
    k[base]      = x1 * cs - x2 * sn;
    k[base + 64] = x2 * cs + x1 * sn;
}

// ---------------------------------------------------------------------------
// Causal flash attention, fp32. 64x64 tiles, D=128, 256 threads.
// ---------------------------------------------------------------------------
#define FDP 132
#define FNP 68
#define FA_SMEM ((64 * FDP * 2 + 64 * FNP) * 4)

__global__ __launch_bounds__(256) void flash_kernel(
    const float* __restrict__ q, const float* __restrict__ k,
    const float* __restrict__ v, float* __restrict__ o)
{
    extern __shared__ float sm[];
    float* Qs  = sm;
    float* KVs = sm + 64 * FDP;
    float* Ps  = KVs + 64 * FDP;

    const int tid = threadIdx.x;
    const int ty = tid >> 4, tx = tid & 15;
    const int iblk = blockIdx.x;                 // query tile
    const int bh = blockIdx.y;
    const int b = bh >> 4, h = bh & 15;
    const size_t rowbase = (size_t)b * SEQ;
    const int m0 = iblk * 64;
    const float scale = 0.08838834764831845f;    // 1/sqrt(128)

    #pragma unroll
    for (int i = 0; i < 8; i++) {
        int lin = tid + 256 * i;
        int r = lin >> 5, c4 = (lin & 31) << 2;
        float4 vq = *(const float4*)(q + ((rowbase + m0 + r) * EMB + h * DHEAD + c4));
        vq.x *= scale; vq.y *= scale; vq.z *= scale; vq.w *= scale;
        *(float4*)&Qs[r * FDP + c4] = vq;
    }

    float m_i[4], l_i[4], acc[4][8];
    #pragma unroll
    for (int i = 0; i < 4; i++) {
        m_i[i] = -1e30f; l_i[i] = 0.f;
        #pragma unroll
        for (int d = 0; d < 8; d++) acc[i][d] = 0.f;
    }
    __syncthreads();

    for (int j = 0; j <= iblk; j++) {
        #pragma unroll
        for (int i = 0; i < 8; i++) {
            int lin = tid + 256 * i;
            int r = lin >> 5, c4 = (lin & 31) << 2;
            *(float4*)&KVs[r * FDP + c4] =
                *(const float4*)(k + ((rowbase + j * 64 + r) * EMB + h * DHEAD + c4));
        }
        __syncthreads();

        float s[4][4];
        #pragma unroll
        for (int i = 0; i < 4; i++)
            #pragma unroll
            for (int jj = 0; jj < 4; jj++) s[i][jj] = 0.f;

        for (int d = 0; d < DHEAD; d += 4) {
            float4 qa[4], kb[4];
            #pragma unroll
            for (int i = 0; i < 4; i++) qa[i] = *(const float4*)&Qs[(ty * 4 + i) * FDP + d];
            #pragma unroll
            for (int i = 0; i < 4; i++) kb[i] = *(const float4*)&KVs[(tx * 4 + i) * FDP + d];
            #pragma unroll
            for (int i = 0; i < 4; i++)
                #pragma unroll
                for (int jj = 0; jj < 4; jj++)
                    s[i][jj] += qa[i].x * kb[jj].x + qa[i].y * kb[jj].y +
                                qa[i].z * kb[jj].z + qa[i].w * kb[jj].w;
        }

        if (j == iblk) {
            #pragma unroll
            for (int i = 0; i < 4; i++)
                #pragma unroll
                for (int jj = 0; jj < 4; jj++)
                    if (j * 64 + tx * 4 + jj > m0 + ty * 4 + i) s[i][jj] = -1e30f;
        }

        float alpha[4];
        #pragma unroll
        for (int i = 0; i < 4; i++) {
            float rm = fmaxf(fmaxf(s[i][0], s[i][1]), fmaxf(s[i][2], s[i][3]));
            #pragma unroll
            for (int off = 1; off < 16; off <<= 1)
                rm = fmaxf(rm, __shfl_xor_sync(0xffffffffu, rm, off));
            float mnew = fmaxf(m_i[i], rm);
            alpha[i] = __expf(m_i[i] - mnew);
            m_i[i] = mnew;
            float rs = 0.f;
            #pragma unroll
            for (int jj = 0; jj < 4; jj++) {
                float p = __expf(s[i][jj] - mnew);
                s[i][jj] = p;
                rs += p;
            }
            #pragma unroll
            for (int off = 1; off < 16; off <<= 1)
                rs += __shfl_xor_sync(0xffffffffu, rs, off);
            l_i[i] = l_i[i] * alpha[i] + rs;
            #pragma unroll
            for (int jj = 0; jj < 4; jj++)
                Ps[(ty * 4 + i) * FNP + tx * 4 + jj] = s[i][jj];
            #pragma unroll
            for (int d = 0; d < 8; d++) acc[i][d] *= alpha[i];
        }
        __syncthreads();

        #pragma unroll
        for (int i = 0; i < 8; i++) {
            int lin = tid + 256 * i;
            int r = lin >> 5, c4 = (lin & 31) << 2;
            *(float4*)&KVs[r * FDP + c4] =
                *(const float4*)(v + ((rowbase + j * 64 + r) * EMB + h * DHEAD + c4));
        }
        __syncthreads();

        for (int n = 0; n < 64; n++) {
            float p[4];
            #pragma unroll
            for (int i = 0; i < 4; i++) p[i] = Ps[(ty * 4 + i) * FNP + n];
            float4 va = *(const float4*)&KVs[n * FDP + tx * 8];
            float4 vb = *(const float4*)&KVs[n * FDP + tx * 8 + 4];
            #pragma unroll
            for (int i = 0; i < 4; i++) {
                acc[i][0] += p[i] * va.x; acc[i][1] += p[i] * va.y;
                acc[i][2] += p[i] * va.z; acc[i][3] += p[i] * va.w;
                acc[i][4] += p[i] * vb.x; acc[i][5] += p[i] * vb.y;
                acc[i][6] += p[i] * vb.z; acc[i][7] += p[i] * vb.w;
            }
        }
        __syncthreads();
    }

    #pragma unroll
    for (int i = 0; i < 4; i++) {
        float invl = 1.f / l_i[i];
        size_t base = (rowbase + m0 + ty * 4 + i) * EMB + h * DHEAD + tx * 8;
        #pragma unroll
        for (int d = 0; d < 8; d++)
            o[base + d] = acc[i][d] * invl;
    }
}

// ---------------------------------------------------------------------------
extern "C" void kernel_launch(void* const* d_in, const int* in_sizes, int n_in,
                              void* d_out, int out_size)
{
    const float* x    = (const float*)d_in[0];
    const float* mask = (const float*)d_in[1];
    const float* Wq = (const float*)d_in[2];  const float* bq = (const float*)d_in[3];
    const float* Aq = (const float*)d_in[4];  const float* Bq = (const float*)d_in[5];
    const float* Cq = (const float*)d_in[6];  const float* Rq = (const float*)d_in[7];
    const float* Wk = (const float*)d_in[8];  const float* bk = (const float*)d_in[9];
    const float* Ak = (const float*)d_in[10]; const float* Bk = (const float*)d_in[11];
    const float* Ck = (const float*)d_in[12]; const float* Rk = (const float*)d_in[13];
    const float* Wv = (const float*)d_in[14]; const float* bv = (const float*)d_in[15];
    const float* Av = (const float*)d_in[16]; const float* Bv = (const float*)d_in[17];
    const float* Cv = (const float*)d_in[18]; const float* Rv = (const float*)d_in[19];
    const float* Wo = (const float*)d_in[20]; const float* Ao = (const float*)d_in[21];
    const float* Bo = (const float*)d_in[22]; const float* Co = (const float*)d_in[23];
    const float* Ro = (const float*)d_in[24];

    float *q, *k, *v, *att, *hx;
    cudaGetSymbolAddress((void**)&q,   g_q);
    cudaGetSymbolAddress((void**)&k,   g_k);
    cudaGetSymbolAddress((void**)&v,   g_v);
    cudaGetSymbolAddress((void**)&att, g_att);
    cudaGetSymbolAddress((void**)&hx,  g_haux);
    float* hq = hx;
    float* hk = hx + (size_t)ROWS * 96;
    float* hv = hx + (size_t)ROWS * 96 * 2;
    float* ho = hx + (size_t)ROWS * 96 * 3;

    cudaFuncSetAttribute(flash_kernel,
                         cudaFuncAttributeMaxDynamicSharedMemorySize, FA_SMEM);

    dim3 ggrid(EMB / BN, ROWS / BM);   // (8, 32)

    // aux terms for q/k/v (one tiled GEMM, silu+mask fused)
    aux_gemm<<<dim3(3, ROWS / 128), 256>>>(x, mask, Aq, Cq, Ak, Ck, Av, Cv, hq, hk, hv);
    // projections (K-augmented GEMMs)
    gemm_aug<<<ggrid, 256>>>(x, hq, Wq, Bq, Rq, bq, q);
    gemm_aug<<<ggrid, 256>>>(x, hk, Wk, Bk, Rk, bk, k);
    gemm_aug<<<ggrid, 256>>>(x, hv, Wv, Bv, Rv, bv, v);
    // rope on q,k
    rope_kernel<<<(ROWS * NHEAD * 64 + 255) / 256, 256>>>(q, k);
    // causal flash attention
    flash_kernel<<<dim3(SEQ / 64, BATCH * NHEAD), 256, FA_SMEM>>>(q, k, v, att);
    // output projection aux + GEMM (no bias)
    aux_gemm<<<dim3(1, ROWS / 128), 256>>>(att, mask, Ao, Co, Ao, Co, Ao, Co, ho, ho, ho);
    gemm_aug<<<ggrid, 256>>>(att, ho, Wo, Bo, Ro, nullptr, (float*)d_out);
}

// round 4
// speedup vs baseline: 2.1993x; 1.5588x over previous
#include <cuda_runtime.h>
#include <cuda_bf16.h>
#include <cstdint>
#include <math.h>

// Problem constants
#define BATCH 2
#define SEQ   2048
#define EMB   2048
#define NHEAD 16
#define DHEAD 128
#define NEXP_ 64
#define RLORA 32
#define ROWS  4096          // BATCH*SEQ
#define KAUG  2144          // EMB + RLORA + NEXP_

// ---------------- scratch (static device globals; no allocations) ----------
__device__ float g_q[(size_t)ROWS * EMB];
__device__ float g_k[(size_t)ROWS * EMB];
__device__ float g_v[(size_t)ROWS * EMB];
__device__ float g_att[(size_t)ROWS * EMB];
__device__ float g_haux[4][(size_t)ROWS * 96];   // per-proj [silu(xA^T)|silu(xC^T)*mask]

// ---------------------------------------------------------------------------
// helpers for split-bf16 mma
// ---------------------------------------------------------------------------
__device__ __forceinline__ unsigned pack_bf2(__nv_bfloat16 a, __nv_bfloat16 b) {
    return (unsigned)__bfloat16_as_ushort(a) | ((unsigned)__bfloat16_as_ushort(b) << 16);
}

__device__ __forceinline__ void mma_bf16(float* c, const unsigned* a, const unsigned* b) {
    asm volatile(
        "mma.sync.aligned.m16n8k16.row.col.f32.bf16.bf16.f32 "
        "{%0,%1,%2,%3}, {%4,%5,%6,%7}, {%8,%9}, {%0,%1,%2,%3};"
        : "+f"(c[0]), "+f"(c[1]), "+f"(c[2]), "+f"(c[3])
        : "r"(a[0]), "r"(a[1]), "r"(a[2]), "r"(a[3]), "r"(b[0]), "r"(b[1]));
}

// ---------------------------------------------------------------------------
// aux GEMM: h[row, 0:32]  = silu(x@A^T)
//           h[row, 32:96] = silu(x@C^T)*mask
// Tiled GEMM 128x96x16, 256 threads, 8x6 microtile. blockIdx.x selects proj.
// ---------------------------------------------------------------------------
__global__ __launch_bounds__(256) void aux_gemm(
    const float* __restrict__ act, const float* __restrict__ mask,
    const float* __restrict__ A0, const float* __restrict__ C0,
    const float* __restrict__ A1, const float* __restrict__ C1,
    const float* __restrict__ A2, const float* __restrict__ C2,
    float* __restrict__ h0, float* __restrict__ h1, float* __restrict__ h2)
{
    __shared__ float As[16][132];
    __shared__ float Bs[16][100];

    const int proj = blockIdx.x;
    const int m0 = blockIdx.y * 128;
    const float* A = (proj == 0) ? A0 : ((proj == 1) ? A1 : A2);
    const float* C = (proj == 0) ? C0 : ((proj == 1) ? C1 : C2);
    float* hout    = (proj == 0) ? h0 : ((proj == 1) ? h1 : h2);

    const int tid = threadIdx.x;
    const int ty = tid >> 4, tx = tid & 15;

    float acc[8][6];
    #pragma unroll
    for (int i = 0; i < 8; i++)
        #pragma unroll
        for (int j = 0; j < 6; j++) acc[i][j] = 0.f;

    for (int k0 = 0; k0 < EMB; k0 += 16) {
        #pragma unroll
        for (int i = 0; i < 2; i++) {
            int lin = tid + 256 * i;
            int r = lin >> 2, c4 = (lin & 3) << 2;
            float4 va = *(const float4*)(act + (size_t)(m0 + r) * EMB + k0 + c4);
            As[c4 + 0][r] = va.x; As[c4 + 1][r] = va.y;
            As[c4 + 2][r] = va.z; As[c4 + 3][r] = va.w;
        }
        #pragma unroll
        for (int i = 0; i < 2; i++) {
            int lin = tid + 256 * i;
            if (lin < 384) {
                int r = lin >> 2, c4 = (lin & 3) << 2;
                const float* src = (r < 32) ? (A + (size_t)r * EMB)
                                            : (C + (size_t)(r - 32) * EMB);
                float4 vb = *(const float4*)(src + k0 + c4);
                Bs[c4 + 0][r] = vb.x; Bs[c4 + 1][r] = vb.y;
                Bs[c4 + 2][r] = vb.z; Bs[c4 + 3][r] = vb.w;
            }
        }
        __syncthreads();

        #pragma unroll
        for (int kk = 0; kk < 16; kk++) {
            float a[8], b[6];
            *(float4*)&a[0] = *(const float4*)&As[kk][ty * 8];
            *(float4*)&a[4] = *(const float4*)&As[kk][ty * 8 + 4];
            #pragma unroll
            for (int j = 0; j < 6; j++) b[j] = Bs[kk][tx * 6 + j];
            #pragma unroll
            for (int i = 0; i < 8; i++)
                #pragma unroll
                for (int j = 0; j < 6; j++)
                    acc[i][j] += a[i] * b[j];
        }
        __syncthreads();
    }

    #pragma unroll
    for (int i = 0; i < 8; i++) {
        int row = m0 + ty * 8 + i;
        #pragma unroll
        for (int j = 0; j < 6; j++) {
            int u = tx * 6 + j;
            float v = acc[i][j];
            float s = v / (1.f + expf(-v));            // silu
            if (u >= 32) s *= mask[(size_t)row * NEXP_ + (u - 32)];
            hout[(size_t)row * 96 + u] = s;
        }
    }
}

// ---------------------------------------------------------------------------
// K-augmented GEMM on tensor cores (split-bf16, 3x mma for fp32-ish accuracy)
//   out[M=4096, N=2048] = sum_k a(m,k) * w(n,k) (+ bias[n])
//   k in [0,2048)      : a = act,  w = W
//   k in [2048,2080)   : a = haux, w = Bl (LoRA up)
//   k in [2080,2144)   : a = haux, w = Rr (expert rows)
// Block 128x128x32, 8 warps, warp tile 32x64, m16n8k16 bf16 mma.
// ---------------------------------------------------------------------------
#define GP 20   // smem pitch in 32-bit words (= 40 bf16)

__global__ __launch_bounds__(256, 2) void gemm_mma(
    const float* __restrict__ act, const float* __restrict__ haux,
    const float* __restrict__ Wd,  const float* __restrict__ Bl,
    const float* __restrict__ Rr,  const float* __restrict__ bias,
    float* __restrict__ out)
{
    __shared__ unsigned As_hi[128][GP], As_lo[128][GP];
    __shared__ unsigned Bs_hi[128][GP], Bs_lo[128][GP];

    const int tid = threadIdx.x;
    const int lane = tid & 31, wid = tid >> 5;
    const int l4 = lane >> 2, lk = lane & 3;
    const int warp_m = wid & 3, warp_n = wid >> 2;     // 4 x 2 warp grid
    const int m0 = blockIdx.y * 128, n0 = blockIdx.x * 128;

    float c[2][8][4];
    #pragma unroll
    for (int mt = 0; mt < 2; mt++)
        #pragma unroll
        for (int nt = 0; nt < 8; nt++)
            #pragma unroll
            for (int i = 0; i < 4; i++) c[mt][nt][i] = 0.f;

    for (int k0 = 0; k0 < KAUG; k0 += 32) {
        const float* asrc; int lda, kof;
        if (k0 < EMB) { asrc = act;  lda = EMB; kof = k0; }
        else          { asrc = haux; lda = 96;  kof = k0 - EMB; }

        const float* wsrc; int ldw, kofw;
        if (k0 < EMB)              { wsrc = Wd; ldw = EMB;   kofw = k0; }
        else if (k0 < EMB + RLORA) { wsrc = Bl; ldw = RLORA; kofw = k0 - EMB; }
        else                       { wsrc = Rr; ldw = NEXP_; kofw = k0 - EMB - RLORA; }

        // load + split A: 128 rows x 32 k = 1024 float4 slots
        #pragma unroll
        for (int i = 0; i < 4; i++) {
            int lin = tid + 256 * i;
            int r = lin >> 3, c4 = (lin & 7) << 2;   // c4 in {0,4,...,28}
            float4 va = *(const float4*)(asrc + (size_t)(m0 + r) * lda + kof + c4);
            __nv_bfloat16 hx = __float2bfloat16_rn(va.x);
            __nv_bfloat16 hy = __float2bfloat16_rn(va.y);
            __nv_bfloat16 hz = __float2bfloat16_rn(va.z);
            __nv_bfloat16 hw = __float2bfloat16_rn(va.w);
            __nv_bfloat16 lx = __float2bfloat16_rn(va.x - __bfloat162float(hx));
            __nv_bfloat16 ly = __float2bfloat16_rn(va.y - __bfloat162float(hy));
            __nv_bfloat16 lz = __float2bfloat16_rn(va.z - __bfloat162float(hz));
            __nv_bfloat16 lw = __float2bfloat16_rn(va.w - __bfloat162float(hw));
            int wofs = c4 >> 1;                      // word offset (even)
            *(uint2*)&As_hi[r][wofs] = make_uint2(pack_bf2(hx, hy), pack_bf2(hz, hw));
            *(uint2*)&As_lo[r][wofs] = make_uint2(pack_bf2(lx, ly), pack_bf2(lz, lw));
        }
        // load + split B (weights, row = output col)
        #pragma unroll
        for (int i = 0; i < 4; i++) {
            int lin = tid + 256 * i;
            int r = lin >> 3, c4 = (lin & 7) << 2;
            float4 vb = *(const float4*)(wsrc + (size_t)(n0 + r) * ldw + kofw + c4);
            __nv_bfloat16 hx = __float2bfloat16_rn(vb.x);
            __nv_bfloat16 hy = __float2bfloat16_rn(vb.y);
            __nv_bfloat16 hz = __float2bfloat16_rn(vb.z);
            __nv_bfloat16 hw = __float2bfloat16_rn(vb.w);
            __nv_bfloat16 lx = __float2bfloat16_rn(vb.x - __bfloat162float(hx));
            __nv_bfloat16 ly = __float2bfloat16_rn(vb.y - __bfloat162float(hy));
            __nv_bfloat16 lz = __float2bfloat16_rn(vb.z - __bfloat162float(hz));
            __nv_bfloat16 lw = __float2bfloat16_rn(vb.w - __bfloat162float(hw));
            int wofs = c4 >> 1;
            *(uint2*)&Bs_hi[r][wofs] = make_uint2(pack_bf2(hx, hy), pack_bf2(hz, hw));
            *(uint2*)&Bs_lo[r][wofs] = make_uint2(pack_bf2(lx, ly), pack_bf2(lz, lw));
        }
        __syncthreads();

        // two k16 steps per 32-k tile
        #pragma unroll
        for (int ks = 0; ks < 2; ks++) {
            const int kw = ks * 8;   // word offset of this k16 step
            unsigned a_hi[2][4], a_lo[2][4];
            #pragma unroll
            for (int mt = 0; mt < 2; mt++) {
                int rb = warp_m * 32 + mt * 16 + l4;
                a_hi[mt][0] = As_hi[rb][kw + lk];
                a_hi[mt][1] = As_hi[rb + 8][kw + lk];
                a_hi[mt][2] = As_hi[rb][kw + 4 + lk];
                a_hi[mt][3] = As_hi[rb + 8][kw + 4 + lk];
                a_lo[mt][0] = As_lo[rb][kw + lk];
                a_lo[mt][1] = As_lo[rb + 8][kw + lk];
                a_lo[mt][2] = As_lo[rb][kw + 4 + lk];
                a_lo[mt][3] = As_lo[rb + 8][kw + 4 + lk];
            }
            #pragma unroll
            for (int nt = 0; nt < 8; nt++) {
                int cb = warp_n * 64 + nt * 8 + l4;
                unsigned b_hi[2], b_lo[2];
                b_hi[0] = Bs_hi[cb][kw + lk];
                b_hi[1] = Bs_hi[cb][kw + 4 + lk];
                b_lo[0] = Bs_lo[cb][kw + lk];
                b_lo[1] = Bs_lo[cb][kw + 4 + lk];
                #pragma unroll
                for (int mt = 0; mt < 2; mt++) {
                    mma_bf16(c[mt][nt], a_hi[mt], b_hi);
                    mma_bf16(c[mt][nt], a_hi[mt], b_lo);
                    mma_bf16(c[mt][nt], a_lo[mt], b_hi);
                }
            }
        }
        __syncthreads();
    }

    // epilogue: bias + store (fp32)
    float2 bv[8];
    #pragma unroll
    for (int nt = 0; nt < 8; nt++) {
        int col = n0 + warp_n * 64 + nt * 8 + 2 * lk;
        if (bias) bv[nt] = *(const float2*)(bias + col);
        else      bv[nt] = make_float2(0.f, 0.f);
    }
    #pragma unroll
    for (int mt = 0; mt < 2; mt++) {
        int r0 = m0 + warp_m * 32 + mt * 16 + l4;
        #pragma unroll
        for (int nt = 0; nt < 8; nt++) {
            int col = n0 + warp_n * 64 + nt * 8 + 2 * lk;
            float2 o0 = make_float2(c[mt][nt][0] + bv[nt].x, c[mt][nt][1] + bv[nt].y);
            float2 o1 = make_float2(c[mt][nt][2] + bv[nt].x, c[mt][nt][3] + bv[nt].y);
            *(float2*)(out + (size_t)r0 * EMB + col)       = o0;
            *(float2*)(out + (size_t)(r0 + 8) * EMB + col) = o1;
        }
    }
}

// ---------------------------------------------------------------------------
// RoPE (in-place on q and k): llama rotate_half form
// ---------------------------------------------------------------------------
__global__ void rope_kernel(float* __restrict__ q, float* __restrict__ k)
{
    int idx = blockIdx.x * blockDim.x + threadIdx.x;   // ROWS*NHEAD*64
    if (idx >= ROWS * NHEAD * 64) return;
    int j   = idx & 63;
    int h   = (idx >> 6) & 15;
    int row = idx >> 10;
    int s   = row & (SEQ - 1);

    float e   = (float)(2 * j) * (1.0f / 128.0f);
    float inv = powf(10000.0f, -e);
    float ang = (float)s * inv;
    float sn, cs;
    sincosf(ang, &sn, &cs);

    size_t base = (size_t)row * EMB + h * DHEAD + j;
    float x1 = q[base], x2 = q[base + 64];
    q[base]      = x1 * cs - x2 * sn;
    q[base + 64] = x2 * cs + x1 * sn;
    x1 = k[base]; x2 = k[base + 64];
    k[base]      = x1 * cs - x2 * sn;
    k[base + 64] = x2 * cs + x1 * sn;
}

// ---------------------------------------------------------------------------
// Causal flash attention, fp32. 64x64 tiles, D=128, 256 threads.
// ---------------------------------------------------------------------------
#define FDP 132
#define FNP 68
#define FA_SMEM ((64 * FDP * 2 + 64 * FNP) * 4)

__global__ __launch_bounds__(256) void flash_kernel(
    const float* __restrict__ q, const float* __restrict__ k,
    const float* __restrict__ v, float* __restrict__ o)
{
    extern __shared__ float sm[];
    float* Qs  = sm;
    float* KVs = sm + 64 * FDP;
    float* Ps  = KVs + 64 * FDP;

    const int tid = threadIdx.x;
    const int ty = tid >> 4, tx = tid & 15;
    const int iblk = blockIdx.x;                 // query tile
    const int bh = blockIdx.y;
    const int b = bh >> 4, h = bh & 15;
    const size_t rowbase = (size_t)b * SEQ;
    const int m0 = iblk * 64;
    const float scale = 0.08838834764831845f;    // 1/sqrt(128)

    #pragma unroll
    for (int i = 0; i < 8; i++) {
        int lin = tid + 256 * i;
        int r = lin >> 5, c4 = (lin & 31) << 2;
        float4 vq = *(const float4*)(q + ((rowbase + m0 + r) * EMB + h * DHEAD + c4));
        vq.x *= scale; vq.y *= scale; vq.z *= scale; vq.w *= scale;
        *(float4*)&Qs[r * FDP + c4] = vq;
    }

    float m_i[4], l_i[4], acc[4][8];
    #pragma unroll
    for (int i = 0; i < 4; i++) {
        m_i[i] = -1e30f; l_i[i] = 0.f;
        #pragma unroll
        for (int d = 0; d < 8; d++) acc[i][d] = 0.f;
    }
    __syncthreads();

    for (int j = 0; j <= iblk; j++) {
        #pragma unroll
        for (int i = 0; i < 8; i++) {
            int lin = tid + 256 * i;
            int r = lin >> 5, c4 = (lin & 31) << 2;
            *(float4*)&KVs[r * FDP + c4] =
                *(const float4*)(k + ((rowbase + j * 64 + r) * EMB + h * DHEAD + c4));
        }
        __syncthreads();

        float s[4][4];
        #pragma unroll
        for (int i = 0; i < 4; i++)
            #pragma unroll
            for (int jj = 0; jj < 4; jj++) s[i][jj] = 0.f;

        for (int d = 0; d < DHEAD; d += 4) {
            float4 qa[4], kb[4];
            #pragma unroll
            for (int i = 0; i < 4; i++) qa[i] = *(const float4*)&Qs[(ty * 4 + i) * FDP + d];
            #pragma unroll
            for (int i = 0; i < 4; i++) kb[i] = *(const float4*)&KVs[(tx * 4 + i) * FDP + d];
            #pragma unroll
            for (int i = 0; i < 4; i++)
                #pragma unroll
                for (int jj = 0; jj < 4; jj++)
                    s[i][jj] += qa[i].x * kb[jj].x + qa[i].y * kb[jj].y +
                                qa[i].z * kb[jj].z + qa[i].w * kb[jj].w;
        }

        if (j == iblk) {
            #pragma unroll
            for (int i = 0; i < 4; i++)
                #pragma unroll
                for (int jj = 0; jj < 4; jj++)
                    if (j * 64 + tx * 4 + jj > m0 + ty * 4 + i) s[i][jj] = -1e30f;
        }

        float alpha[4];
        #pragma unroll
        for (int i = 0; i < 4; i++) {
            float rm = fmaxf(fmaxf(s[i][0], s[i][1]), fmaxf(s[i][2], s[i][3]));
            #pragma unroll
            for (int off = 1; off < 16; off <<= 1)
                rm = fmaxf(rm, __shfl_xor_sync(0xffffffffu, rm, off));
            float mnew = fmaxf(m_i[i], rm);
            alpha[i] = __expf(m_i[i] - mnew);
            m_i[i] = mnew;
            float rs = 0.f;
            #pragma unroll
            for (int jj = 0; jj < 4; jj++) {
                float p = __expf(s[i][jj] - mnew);
                s[i][jj] = p;
                rs += p;
            }
            #pragma unroll
            for (int off = 1; off < 16; off <<= 1)
                rs += __shfl_xor_sync(0xffffffffu, rs, off);
            l_i[i] = l_i[i] * alpha[i] + rs;
            #pragma unroll
            for (int jj = 0; jj < 4; jj++)
                Ps[(ty * 4 + i) * FNP + tx * 4 + jj] = s[i][jj];
            #pragma unroll
            for (int d = 0; d < 8; d++) acc[i][d] *= alpha[i];
        }
        __syncthreads();

        #pragma unroll
        for (int i = 0; i < 8; i++) {
            int lin = tid + 256 * i;
            int r = lin >> 5, c4 = (lin & 31) << 2;
            *(float4*)&KVs[r * FDP + c4] =
                *(const float4*)(v + ((rowbase + j * 64 + r) * EMB + h * DHEAD + c4));
        }
        __syncthreads();

        for (int n = 0; n < 64; n++) {
            float p[4];
            #pragma unroll
            for (int i = 0; i < 4; i++) p[i] = Ps[(ty * 4 + i) * FNP + n];
            float4 va = *(const float4*)&KVs[n * FDP + tx * 8];
            float4 vb = *(const float4*)&KVs[n * FDP + tx * 8 + 4];
            #pragma unroll
            for (int i = 0; i < 4; i++) {
                acc[i][0] += p[i] * va.x; acc[i][1] += p[i] * va.y;
                acc[i][2] += p[i] * va.z; acc[i][3] += p[i] * va.w;
                acc[i][4] += p[i] * vb.x; acc[i][5] += p[i] * vb.y;
                acc[i][6] += p[i] * vb.z; acc[i][7] += p[i] * vb.w;
            }
        }
        __syncthreads();
    }

    #pragma unroll
    for (int i = 0; i < 4; i++) {
        float invl = 1.f / l_i[i];
        size_t base = (rowbase + m0 + ty * 4 + i) * EMB + h * DHEAD + tx * 8;
        #pragma unroll
        for (int d = 0; d < 8; d++)
            o[base + d] = acc[i][d] * invl;
    }
}

// ---------------------------------------------------------------------------
extern "C" void kernel_launch(void* const* d_in, const int* in_sizes, int n_in,
                              void* d_out, int out_size)
{
    const float* x    = (const float*)d_in[0];
    const float* mask = (const float*)d_in[1];
    const float* Wq = (const float*)d_in[2];  const float* bq = (const float*)d_in[3];
    const float* Aq = (const float*)d_in[4];  const float* Bq = (const float*)d_in[5];
    const float* Cq = (const float*)d_in[6];  const float* Rq = (const float*)d_in[7];
    const float* Wk = (const float*)d_in[8];  const float* bk = (const float*)d_in[9];
    const float* Ak = (const float*)d_in[10]; const float* Bk = (const float*)d_in[11];
    const float* Ck = (const float*)d_in[12]; const float* Rk = (const float*)d_in[13];
    const float* Wv = (const float*)d_in[14]; const float* bv = (const float*)d_in[15];
    const float* Av = (const float*)d_in[16]; const float* Bv = (const float*)d_in[17];
    const float* Cv = (const float*)d_in[18]; const float* Rv = (const float*)d_in[19];
    const float* Wo = (const float*)d_in[20]; const float* Ao = (const float*)d_in[21];
    const float* Bo = (const float*)d_in[22]; const float* Co = (const float*)d_in[23];
    const float* Ro = (const float*)d_in[24];

    float *q, *k, *v, *att, *hx;
    cudaGetSymbolAddress((void**)&q,   g_q);
    cudaGetSymbolAddress((void**)&k,   g_k);
    cudaGetSymbolAddress((void**)&v,   g_v);
    cudaGetSymbolAddress((void**)&att, g_att);
    cudaGetSymbolAddress((void**)&hx,  g_haux);
    float* hq = hx;
    float* hk = hx + (size_t)ROWS * 96;
    float* hv = hx + (size_t)ROWS * 96 * 2;
    float* ho = hx + (size_t)ROWS * 96 * 3;

    cudaFuncSetAttribute(flash_kernel,
                         cudaFuncAttributeMaxDynamicSharedMemorySize, FA_SMEM);

    dim3 ggrid(EMB / 128, ROWS / 128);   // (16, 32)

    // aux terms for q/k/v (one tiled GEMM, silu+mask fused)
    aux_gemm<<<dim3(3, ROWS / 128), 256>>>(x, mask, Aq, Cq, Ak, Ck, Av, Cv, hq, hk, hv);
    // projections (K-augmented GEMMs, split-bf16 tensor cores)
    gemm_mma<<<ggrid, 256>>>(x, hq, Wq, Bq, Rq, bq, q);
    gemm_mma<<<ggrid, 256>>>(x, hk, Wk, Bk, Rk, bk, k);
    gemm_mma<<<ggrid, 256>>>(x, hv, Wv, Bv, Rv, bv, v);
    // rope on q,k
    rope_kernel<<<(ROWS * NHEAD * 64 + 255) / 256, 256>>>(q, k);
    // causal flash attention
    flash_kernel<<<dim3(SEQ / 64, BATCH * NHEAD), 256, FA_SMEM>>>(q, k, v, att);
    // output projection aux + GEMM (no bias)
    aux_gemm<<<dim3(1, ROWS / 128), 256>>>(att, mask, Ao, Co, Ao, Co, Ao, Co, ho, ho, ho);
    gemm_mma<<<ggrid, 256>>>(att, ho, Wo, Bo, Ro, nullptr, (float*)d_out);
}

// round 5
// speedup vs baseline: 3.6355x; 1.6531x over previous
#include <cuda_runtime.h>
#include <cuda_bf16.h>
#include <cstdint>
#include <math.h>

// Problem constants
#define BATCH 2
#define SEQ   2048
#define EMB   2048
#define NHEAD 16
#define DHEAD 128
#define NEXP_ 64
#define RLORA 32
#define ROWS  4096          // BATCH*SEQ
#define KAUG  2144          // EMB + RLORA + NEXP_

// ---------------- scratch (static device globals; no allocations) ----------
__device__ float g_q[(size_t)ROWS * EMB];
__device__ float g_k[(size_t)ROWS * EMB];
__device__ float g_v[(size_t)ROWS * EMB];
__device__ float g_att[(size_t)ROWS * EMB];
__device__ float g_haux[4][(size_t)ROWS * 96];   // per-proj [silu(xA^T)|silu(xC^T)*mask]

// ---------------------------------------------------------------------------
// helpers for split-bf16 mma
// ---------------------------------------------------------------------------
__device__ __forceinline__ unsigned pack_bf2(__nv_bfloat16 a, __nv_bfloat16 b) {
    return (unsigned)__bfloat16_as_ushort(a) | ((unsigned)__bfloat16_as_ushort(b) << 16);
}

// split a float into bf16 hi and bf16 lo (residual)
__device__ __forceinline__ void split_bf(float x, __nv_bfloat16& hi, __nv_bfloat16& lo) {
    hi = __float2bfloat16_rn(x);
    lo = __float2bfloat16_rn(x - __bfloat162float(hi));
}

__device__ __forceinline__ void mma_bf16(float* c, const unsigned* a, const unsigned* b) {
    asm volatile(
        "mma.sync.aligned.m16n8k16.row.col.f32.bf16.bf16.f32 "
        "{%0,%1,%2,%3}, {%4,%5,%6,%7}, {%8,%9}, {%0,%1,%2,%3};"
        : "+f"(c[0]), "+f"(c[1]), "+f"(c[2]), "+f"(c[3])
        : "r"(a[0]), "r"(a[1]), "r"(a[2]), "r"(a[3]), "r"(b[0]), "r"(b[1]));
}

// ---------------------------------------------------------------------------
// aux GEMM: h[row, 0:32]  = silu(x@A^T)
//           h[row, 32:96] = silu(x@C^T)*mask
// ---------------------------------------------------------------------------
__global__ __launch_bounds__(256) void aux_gemm(
    const float* __restrict__ act, const float* __restrict__ mask,
    const float* __restrict__ A0, const float* __restrict__ C0,
    const float* __restrict__ A1, const float* __restrict__ C1,
    const float* __restrict__ A2, const float* __restrict__ C2,
    float* __restrict__ h0, float* __restrict__ h1, float* __restrict__ h2)
{
    __shared__ float As[16][132];
    __shared__ float Bs[16][100];

    const int proj = blockIdx.x;
    const int m0 = blockIdx.y * 128;
    const float* A = (proj == 0) ? A0 : ((proj == 1) ? A1 : A2);
    const float* C = (proj == 0) ? C0 : ((proj == 1) ? C1 : C2);
    float* hout    = (proj == 0) ? h0 : ((proj == 1) ? h1 : h2);

    const int tid = threadIdx.x;
    const int ty = tid >> 4, tx = tid & 15;

    float acc[8][6];
    #pragma unroll
    for (int i = 0; i < 8; i++)
        #pragma unroll
        for (int j = 0; j < 6; j++) acc[i][j] = 0.f;

    for (int k0 = 0; k0 < EMB; k0 += 16) {
        #pragma unroll
        for (int i = 0; i < 2; i++) {
            int lin = tid + 256 * i;
            int r = lin >> 2, c4 = (lin & 3) << 2;
            float4 va = *(const float4*)(act + (size_t)(m0 + r) * EMB + k0 + c4);
            As[c4 + 0][r] = va.x; As[c4 + 1][r] = va.y;
            As[c4 + 2][r] = va.z; As[c4 + 3][r] = va.w;
        }
        #pragma unroll
        for (int i = 0; i < 2; i++) {
            int lin = tid + 256 * i;
            if (lin < 384) {
                int r = lin >> 2, c4 = (lin & 3) << 2;
                const float* src = (r < 32) ? (A + (size_t)r * EMB)
                                            : (C + (size_t)(r - 32) * EMB);
                float4 vb = *(const float4*)(src + k0 + c4);
                Bs[c4 + 0][r] = vb.x; Bs[c4 + 1][r] = vb.y;
                Bs[c4 + 2][r] = vb.z; Bs[c4 + 3][r] = vb.w;
            }
        }
        __syncthreads();

        #pragma unroll
        for (int kk = 0; kk < 16; kk++) {
            float a[8], b[6];
            *(float4*)&a[0] = *(const float4*)&As[kk][ty * 8];
            *(float4*)&a[4] = *(const float4*)&As[kk][ty * 8 + 4];
            #pragma unroll
            for (int j = 0; j < 6; j++) b[j] = Bs[kk][tx * 6 + j];
            #pragma unroll
            for (int i = 0; i < 8; i++)
                #pragma unroll
                for (int j = 0; j < 6; j++)
                    acc[i][j] += a[i] * b[j];
        }
        __syncthreads();
    }

    #pragma unroll
    for (int i = 0; i < 8; i++) {
        int row = m0 + ty * 8 + i;
        #pragma unroll
        for (int j = 0; j < 6; j++) {
            int u = tx * 6 + j;
            float v = acc[i][j];
            float s = v / (1.f + expf(-v));            // silu
            if (u >= 32) s *= mask[(size_t)row * NEXP_ + (u - 32)];
            hout[(size_t)row * 96 + u] = s;
        }
    }
}

// ---------------------------------------------------------------------------
// K-augmented GEMM on tensor cores (split-bf16, 3x mma)
// ---------------------------------------------------------------------------
#define GP 20   // smem pitch in 32-bit words

__global__ __launch_bounds__(256, 2) void gemm_mma(
    const float* __restrict__ act, const float* __restrict__ haux,
    const float* __restrict__ Wd,  const float* __restrict__ Bl,
    const float* __restrict__ Rr,  const float* __restrict__ bias,
    float* __restrict__ out)
{
    __shared__ unsigned As_hi[128][GP], As_lo[128][GP];
    __shared__ unsigned Bs_hi[128][GP], Bs_lo[128][GP];

    const int tid = threadIdx.x;
    const int lane = tid & 31, wid = tid >> 5;
    const int l4 = lane >> 2, lk = lane & 3;
    const int warp_m = wid & 3, warp_n = wid >> 2;     // 4 x 2 warp grid
    const int m0 = blockIdx.y * 128, n0 = blockIdx.x * 128;

    float c[2][8][4];
    #pragma unroll
    for (int mt = 0; mt < 2; mt++)
        #pragma unroll
        for (int nt = 0; nt < 8; nt++)
            #pragma unroll
            for (int i = 0; i < 4; i++) c[mt][nt][i] = 0.f;

    for (int k0 = 0; k0 < KAUG; k0 += 32) {
        const float* asrc; int lda, kof;
        if (k0 < EMB) { asrc = act;  lda = EMB; kof = k0; }
        else          { asrc = haux; lda = 96;  kof = k0 - EMB; }

        const float* wsrc; int ldw, kofw;
        if (k0 < EMB)              { wsrc = Wd; ldw = EMB;   kofw = k0; }
        else if (k0 < EMB + RLORA) { wsrc = Bl; ldw = RLORA; kofw = k0 - EMB; }
        else                       { wsrc = Rr; ldw = NEXP_; kofw = k0 - EMB - RLORA; }

        #pragma unroll
        for (int i = 0; i < 4; i++) {
            int lin = tid + 256 * i;
            int r = lin >> 3, c4 = (lin & 7) << 2;
            float4 va = *(const float4*)(asrc + (size_t)(m0 + r) * lda + kof + c4);
            __nv_bfloat16 hx, lx, hy, ly, hz, lz, hw, lw;
            split_bf(va.x, hx, lx); split_bf(va.y, hy, ly);
            split_bf(va.z, hz, lz); split_bf(va.w, hw, lw);
            int wofs = c4 >> 1;
            *(uint2*)&As_hi[r][wofs] = make_uint2(pack_bf2(hx, hy), pack_bf2(hz, hw));
            *(uint2*)&As_lo[r][wofs] = make_uint2(pack_bf2(lx, ly), pack_bf2(lz, lw));
        }
        #pragma unroll
        for (int i = 0; i < 4; i++) {
            int lin = tid + 256 * i;
            int r = lin >> 3, c4 = (lin & 7) << 2;
            float4 vb = *(const float4*)(wsrc + (size_t)(n0 + r) * ldw + kofw + c4);
            __nv_bfloat16 hx, lx, hy, ly, hz, lz, hw, lw;
            split_bf(vb.x, hx, lx); split_bf(vb.y, hy, ly);
            split_bf(vb.z, hz, lz); split_bf(vb.w, hw, lw);
            int wofs = c4 >> 1;
            *(uint2*)&Bs_hi[r][wofs] = make_uint2(pack_bf2(hx, hy), pack_bf2(hz, hw));
            *(uint2*)&Bs_lo[r][wofs] = make_uint2(pack_bf2(lx, ly), pack_bf2(lz, lw));
        }
        __syncthreads();

        #pragma unroll
        for (int ks = 0; ks < 2; ks++) {
            const int kw = ks * 8;
            unsigned a_hi[2][4], a_lo[2][4];
            #pragma unroll
            for (int mt = 0; mt < 2; mt++) {
                int rb = warp_m * 32 + mt * 16 + l4;
                a_hi[mt][0] = As_hi[rb][kw + lk];
                a_hi[mt][1] = As_hi[rb + 8][kw + lk];
                a_hi[mt][2] = As_hi[rb][kw + 4 + lk];
                a_hi[mt][3] = As_hi[rb + 8][kw + 4 + lk];
                a_lo[mt][0] = As_lo[rb][kw + lk];
                a_lo[mt][1] = As_lo[rb + 8][kw + lk];
                a_lo[mt][2] = As_lo[rb][kw + 4 + lk];
                a_lo[mt][3] = As_lo[rb + 8][kw + 4 + lk];
            }
            #pragma unroll
            for (int nt = 0; nt < 8; nt++) {
                int cb = warp_n * 64 + nt * 8 + l4;
                unsigned b_hi[2], b_lo[2];
                b_hi[0] = Bs_hi[cb][kw + lk];
                b_hi[1] = Bs_hi[cb][kw + 4 + lk];
                b_lo[0] = Bs_lo[cb][kw + lk];
                b_lo[1] = Bs_lo[cb][kw + 4 + lk];
                #pragma unroll
                for (int mt = 0; mt < 2; mt++) {
                    mma_bf16(c[mt][nt], a_hi[mt], b_hi);
                    mma_bf16(c[mt][nt], a_hi[mt], b_lo);
                    mma_bf16(c[mt][nt], a_lo[mt], b_hi);
                }
            }
        }
        __syncthreads();
    }

    float2 bv[8];
    #pragma unroll
    for (int nt = 0; nt < 8; nt++) {
        int col = n0 + warp_n * 64 + nt * 8 + 2 * lk;
        if (bias) bv[nt] = *(const float2*)(bias + col);
        else      bv[nt] = make_float2(0.f, 0.f);
    }
    #pragma unroll
    for (int mt = 0; mt < 2; mt++) {
        int r0 = m0 + warp_m * 32 + mt * 16 + l4;
        #pragma unroll
        for (int nt = 0; nt < 8; nt++) {
            int col = n0 + warp_n * 64 + nt * 8 + 2 * lk;
            float2 o0 = make_float2(c[mt][nt][0] + bv[nt].x, c[mt][nt][1] + bv[nt].y);
            float2 o1 = make_float2(c[mt][nt][2] + bv[nt].x, c[mt][nt][3] + bv[nt].y);
            *(float2*)(out + (size_t)r0 * EMB + col)       = o0;
            *(float2*)(out + (size_t)(r0 + 8) * EMB + col) = o1;
        }
    }
}

// ---------------------------------------------------------------------------
// RoPE (in-place on q and k)
// ---------------------------------------------------------------------------
__global__ void rope_kernel(float* __restrict__ q, float* __restrict__ k)
{
    int idx = blockIdx.x * blockDim.x + threadIdx.x;   // ROWS*NHEAD*64
    if (idx >= ROWS * NHEAD * 64) return;
    int j   = idx & 63;
    int h   = (idx >> 6) & 15;
    int row = idx >> 10;
    int s   = row & (SEQ - 1);

    float e   = (float)(2 * j) * (1.0f / 128.0f);
    float inv = powf(10000.0f, -e);
    float ang = (float)s * inv;
    float sn, cs;
    sincosf(ang, &sn, &cs);

    size_t base = (size_t)row * EMB + h * DHEAD + j;
    float x1 = q[base], x2 = q[base + 64];
    q[base]      = x1 * cs - x2 * sn;
    q[base + 64] = x2 * cs + x1 * sn;
    x1 = k[base]; x2 = k[base + 64];
    k[base]      = x1 * cs - x2 * sn;
    k[base + 64] = x2 * cs + x1 * sn;
}

// ---------------------------------------------------------------------------
// Causal flash attention on tensor cores (split-bf16).
// CTA: 128 q-rows (8 warps x 16), key tiles of 64. Q frags in registers.
// K in smem packed along d (pitch 68 words), V packed along k (pitch 136).
// ---------------------------------------------------------------------------
#define KPP 68
#define VPP 136
#define FA2_SMEM ((64 * KPP * 2 + 32 * VPP * 2) * 4)

__global__ __launch_bounds__(256) void flash_mma(
    const float* __restrict__ q, const float* __restrict__ k,
    const float* __restrict__ v, float* __restrict__ o)
{
    extern __shared__ unsigned sw[];
    unsigned* Kph = sw;
    unsigned* Kpl = Kph + 64 * KPP;
    unsigned* Vph = Kpl + 64 * KPP;
    unsigned* Vpl = Vph + 32 * VPP;

    const int tid = threadIdx.x;
    const int lane = tid & 31, wm = tid >> 5;
    const int l4 = lane >> 2, lk = lane & 3;
    const int iblk = (int)gridDim.x - 1 - (int)blockIdx.x;   // heavy CTAs first
    const int bh = blockIdx.y;
    const int b = bh >> 4, h = bh & 15;
    const size_t rowbase = (size_t)b * SEQ;
    const int m0 = iblk * 128;
    const float scale = 0.08838834764831845f;    // 1/sqrt(128)

    // ---- Q fragments (pre-scaled, split into bf16 hi/lo), registers ----
    unsigned qh[8][4], ql[8][4];
    {
        const int r0 = m0 + wm * 16 + l4;
        #pragma unroll
        for (int s = 0; s < 8; s++) {
            #pragma unroll
            for (int f = 0; f < 4; f++) {
                int r = r0 + ((f & 1) ? 8 : 0);
                int d = 16 * s + 2 * lk + ((f & 2) ? 8 : 0);
                float2 qv = *(const float2*)(q + (rowbase + r) * EMB + h * DHEAD + d);
                float x = qv.x * scale, y = qv.y * scale;
                __nv_bfloat16 hx, lx, hy, ly;
                split_bf(x, hx, lx); split_bf(y, hy, ly);
                qh[s][f] = pack_bf2(hx, hy);
                ql[s][f] = pack_bf2(lx, ly);
            }
        }
    }

    float mr0 = -1e30f, mr1 = -1e30f, lr0 = 0.f, lr1 = 0.f;
    float oacc[16][4];
    #pragma unroll
    for (int nt = 0; nt < 16; nt++)
        #pragma unroll
        for (int i = 0; i < 4; i++) oacc[nt][i] = 0.f;

    const int ntiles = 2 * iblk + 2;
    for (int j = 0; j < ntiles; j++) {
        // ---- load K tile: Kp[key][dw] = pack(K[key][2dw], K[key][2dw+1]) ----
        #pragma unroll
        for (int i = 0; i < 16; i++) {
            int lin = tid + 256 * i;               // 4096 slots
            int n = lin >> 6, dw = lin & 63;
            float2 kv = *(const float2*)(k + (rowbase + j * 64 + n) * EMB + h * DHEAD + 2 * dw);
            __nv_bfloat16 hx, lx, hy, ly;
            split_bf(kv.x, hx, lx); split_bf(kv.y, hy, ly);
            Kph[n * KPP + dw] = pack_bf2(hx, hy);
            Kpl[n * KPP + dw] = pack_bf2(lx, ly);
        }
        // ---- load V tile: Vp[kw][n] = pack(V[2kw][n], V[2kw+1][n]) ----
        #pragma unroll
        for (int i = 0; i < 16; i++) {
            int lin = tid + 256 * i;               // 4096 slots
            int kw = lin >> 7, nn = lin & 127;
            size_t rbase = (rowbase + j * 64 + 2 * kw) * EMB + h * DHEAD + nn;
            float v0 = v[rbase];
            float v1 = v[rbase + EMB];
            __nv_bfloat16 h0, l0, h1, l1;
            split_bf(v0, h0, l0); split_bf(v1, h1, l1);
            Vph[kw * VPP + nn] = pack_bf2(h0, h1);
            Vpl[kw * VPP + nn] = pack_bf2(l0, l1);
        }
        __syncthreads();

        // ---- S = Q K^T  (16x64 per warp; 8 n-tiles of 8) ----
        float sacc[8][4];
        #pragma unroll
        for (int nt = 0; nt < 8; nt++)
            #pragma unroll
            for (int i = 0; i < 4; i++) sacc[nt][i] = 0.f;

        #pragma unroll
        for (int s = 0; s < 8; s++) {
            #pragma unroll
            for (int nt = 0; nt < 8; nt++) {
                int kr = (nt * 8 + l4) * KPP + 8 * s + lk;
                unsigned b_hi[2], b_lo[2];
                b_hi[0] = Kph[kr];
                b_hi[1] = Kph[kr + 4];
                b_lo[0] = Kpl[kr];
                b_lo[1] = Kpl[kr + 4];
                mma_bf16(sacc[nt], qh[s], b_hi);
                mma_bf16(sacc[nt], qh[s], b_lo);
                mma_bf16(sacc[nt], ql[s], b_hi);
            }
        }

        // ---- causal mask (diagonal key tiles only) ----
        if (j >= 2 * iblk) {
            int row0 = m0 + wm * 16 + l4;
            #pragma unroll
            for (int nt = 0; nt < 8; nt++) {
                int col = j * 64 + nt * 8 + 2 * lk;
                if (col     > row0)     sacc[nt][0] = -1e30f;
                if (col + 1 > row0)     sacc[nt][1] = -1e30f;
                if (col     > row0 + 8) sacc[nt][2] = -1e30f;
                if (col + 1 > row0 + 8) sacc[nt][3] = -1e30f;
            }
        }

        // ---- online softmax (rows l4 and l4+8; row-mates = 4 lanes) ----
        float mx0 = -1e30f, mx1 = -1e30f;
        #pragma unroll
        for (int nt = 0; nt < 8; nt++) {
            mx0 = fmaxf(mx0, fmaxf(sacc[nt][0], sacc[nt][1]));
            mx1 = fmaxf(mx1, fmaxf(sacc[nt][2], sacc[nt][3]));
        }
        mx0 = fmaxf(mx0, __shfl_xor_sync(0xffffffffu, mx0, 1));
        mx0 = fmaxf(mx0, __shfl_xor_sync(0xffffffffu, mx0, 2));
        mx1 = fmaxf(mx1, __shfl_xor_sync(0xffffffffu, mx1, 1));
        mx1 = fmaxf(mx1, __shfl_xor_sync(0xffffffffu, mx1, 2));

        float mn0 = fmaxf(mr0, mx0), mn1 = fmaxf(mr1, mx1);
        float al0 = __expf(mr0 - mn0), al1 = __expf(mr1 - mn1);
        mr0 = mn0; mr1 = mn1;

        unsigned ph01[8], pl01[8], ph23[8], pl23[8];
        float rs0 = 0.f, rs1 = 0.f;
        #pragma unroll
        for (int nt = 0; nt < 8; nt++) {
            float p0 = __expf(sacc[nt][0] - mn0);
            float p1 = __expf(sacc[nt][1] - mn0);
            float p2 = __expf(sacc[nt][2] - mn1);
            float p3 = __expf(sacc[nt][3] - mn1);
            rs0 += p0 + p1; rs1 += p2 + p3;
            __nv_bfloat16 h0, l0, h1, l1;
            split_bf(p0, h0, l0); split_bf(p1, h1, l1);
            ph01[nt] = pack_bf2(h0, h1); pl01[nt] = pack_bf2(l0, l1);
            split_bf(p2, h0, l0); split_bf(p3, h1, l1);
            ph23[nt] = pack_bf2(h0, h1); pl23[nt] = pack_bf2(l0, l1);
        }
        rs0 += __shfl_xor_sync(0xffffffffu, rs0, 1);
        rs0 += __shfl_xor_sync(0xffffffffu, rs0, 2);
        rs1 += __shfl_xor_sync(0xffffffffu, rs1, 1);
        rs1 += __shfl_xor_sync(0xffffffffu, rs1, 2);
        lr0 = lr0 * al0 + rs0;
        lr1 = lr1 * al1 + rs1;

        #pragma unroll
        for (int nt = 0; nt < 16; nt++) {
            oacc[nt][0] *= al0; oacc[nt][1] *= al0;
            oacc[nt][2] *= al1; oacc[nt][3] *= al1;
        }

        // ---- O += P V  (A-frags of P come straight from S C-frags) ----
        #pragma unroll
        for (int t = 0; t < 4; t++) {
            unsigned pa_h[4], pa_l[4];
            pa_h[0] = ph01[2 * t];     pa_l[0] = pl01[2 * t];
            pa_h[1] = ph23[2 * t];     pa_l[1] = pl23[2 * t];
            pa_h[2] = ph01[2 * t + 1]; pa_l[2] = pl01[2 * t + 1];
            pa_h[3] = ph23[2 * t + 1]; pa_l[3] = pl23[2 * t + 1];
            #pragma unroll
            for (int nt = 0; nt < 16; nt++) {
                int vr = (8 * t + lk) * VPP + nt * 8 + l4;
                unsigned b_hi[2], b_lo[2];
                b_hi[0] = Vph[vr];
                b_hi[1] = Vph[vr + 4 * VPP];
                b_lo[0] = Vpl[vr];
                b_lo[1] = Vpl[vr + 4 * VPP];
                mma_bf16(oacc[nt], pa_h, b_hi);
                mma_bf16(oacc[nt], pa_l, b_hi);
                mma_bf16(oacc[nt], pa_h, b_lo);
            }
        }
        __syncthreads();
    }

    // ---- epilogue: normalize, store ----
    float il0 = 1.f / lr0, il1 = 1.f / lr1;
    int row0 = m0 + wm * 16 + l4;
    #pragma unroll
    for (int nt = 0; nt < 16; nt++) {
        int col = h * DHEAD + nt * 8 + 2 * lk;
        float2 o0 = make_float2(oacc[nt][0] * il0, oacc[nt][1] * il0);
        float2 o1 = make_float2(oacc[nt][2] * il1, oacc[nt][3] * il1);
        *(float2*)(o + (rowbase + row0) * EMB + col)     = o0;
        *(float2*)(o + (rowbase + row0 + 8) * EMB + col) = o1;
    }
}

// ---------------------------------------------------------------------------
extern "C" void kernel_launch(void* const* d_in, const int* in_sizes, int n_in,
                              void* d_out, int out_size)
{
    const float* x    = (const float*)d_in[0];
    const float* mask = (const float*)d_in[1];
    const float* Wq = (const float*)d_in[2];  const float* bq = (const float*)d_in[3];
    const float* Aq = (const float*)d_in[4];  const float* Bq = (const float*)d_in[5];
    const float* Cq = (const float*)d_in[6];  const float* Rq = (const float*)d_in[7];
    const float* Wk = (const float*)d_in[8];  const float* bk = (const float*)d_in[9];
    const float* Ak = (const float*)d_in[10]; const float* Bk = (const float*)d_in[11];
    const float* Ck = (const float*)d_in[12]; const float* Rk = (const float*)d_in[13];
    const float* Wv = (const float*)d_in[14]; const float* bv = (const float*)d_in[15];
    const float* Av = (const float*)d_in[16]; const float* Bv = (const float*)d_in[17];
    const float* Cv = (const float*)d_in[18]; const float* Rv = (const float*)d_in[19];
    const float* Wo = (const float*)d_in[20]; const float* Ao = (const float*)d_in[21];
    const float* Bo = (const float*)d_in[22]; const float* Co = (const float*)d_in[23];
    const float* Ro = (const float*)d_in[24];

    float *q, *k, *v, *att, *hx;
    cudaGetSymbolAddress((void**)&q,   g_q);
    cudaGetSymbolAddress((void**)&k,   g_k);
    cudaGetSymbolAddress((void**)&v,   g_v);
    cudaGetSymbolAddress((void**)&att, g_att);
    cudaGetSymbolAddress((void**)&hx,  g_haux);
    float* hq = hx;
    float* hk = hx + (size_t)ROWS * 96;
    float* hv = hx + (size_t)ROWS * 96 * 2;
    float* ho = hx + (size_t)ROWS * 96 * 3;

    cudaFuncSetAttribute(flash_mma,
                         cudaFuncAttributeMaxDynamicSharedMemorySize, FA2_SMEM);

    dim3 ggrid(EMB / 128, ROWS / 128);   // (16, 32)

    // aux terms for q/k/v
    aux_gemm<<<dim3(3, ROWS / 128), 256>>>(x, mask, Aq, Cq, Ak, Ck, Av, Cv, hq, hk, hv);
    // projections (K-augmented GEMMs, split-bf16 tensor cores)
    gemm_mma<<<ggrid, 256>>>(x, hq, Wq, Bq, Rq, bq, q);
    gemm_mma<<<ggrid, 256>>>(x, hk, Wk, Bk, Rk, bk, k);
    gemm_mma<<<ggrid, 256>>>(x, hv, Wv, Bv, Rv, bv, v);
    // rope on q,k
    rope_kernel<<<(ROWS * NHEAD * 64 + 255) / 256, 256>>>(q, k);
    // causal flash attention (tensor cores)
    flash_mma<<<dim3(SEQ / 128, BATCH * NHEAD), 256, FA2_SMEM>>>(q, k, v, att);
    // output projection aux + GEMM (no bias)
    aux_gemm<<<dim3(1, ROWS / 128), 256>>>(att, mask, Ao, Co, Ao, Co, Ao, Co, ho, ho, ho);
    gemm_mma<<<ggrid, 256>>>(att, ho, Wo, Bo, Ro, nullptr, (float*)d_out);
}